// round 4
// baseline (speedup 1.0000x reference)
#include <cuda_runtime.h>

#define H        128
#define NROWS    200000
#define M_NODES  1000
#define J_NODES  5000
#define RPW      8                  // rows per warp per pass over W1
#define SBLOCKS  148                // 1 block/SM
#define SWARPS   16                 // warps per score block (512 threads)
#define NWTOT    (SBLOCKS * SWARPS)
#define JB       8                  // rows per precompute block

typedef unsigned long long u64;

// ---------------- device scratch ----------------
__device__ __align__(16) float g_c[H];
__device__ __align__(16) float g_A[M_NODES * H];
__device__ __align__(16) float g_B[J_NODES * H];
__device__ float g_wmax[NWTOT];
__device__ int   g_warg[NWTOT];
__device__ float g_wZ[NWTOT];
__device__ float g_wS1[NWTOT];

// ---------------- packed f32x2 helpers ----------------
__device__ __forceinline__ u64 ffma2(u64 a, u64 b, u64 c) {
    u64 d;
    asm("fma.rn.f32x2 %0, %1, %2, %3;" : "=l"(d) : "l"(a), "l"(b), "l"(c));
    return d;
}
__device__ __forceinline__ float2 unpack2(u64 v) {
    float2 r;
    asm("mov.b64 {%0, %1}, %2;" : "=f"(r.x), "=f"(r.y) : "l"(v));
    return r;
}
__device__ __forceinline__ u64 pack2(float lo, float hi) {
    u64 d;
    asm("mov.b64 %0, {%1, %2};" : "=l"(d) : "f"(lo), "f"(hi));
    return d;
}

// ---------------- K1: precompute cg, A, B ----------------
__global__ void __launch_bounds__(128) precompute_kernel(
        const float* __restrict__ xg,
        const float* __restrict__ xm,
        const float* __restrict__ xj,
        const float* __restrict__ W0,
        const float* __restrict__ b0) {
    const int MB  = M_NODES / JB;   // 125
    const int JBL = J_NODES / JB;   // 625
    int b = blockIdx.x;
    int t = threadIdx.x;
    __shared__ __align__(16) float xs[JB][H];

    if (b < MB + JBL) {
        const float* src; float* dst; int r0, woff;
        if (b < MB) { src = xm; dst = g_A; r0 = b * JB;        woff = 2 * H; }
        else        { src = xj; dst = g_B; r0 = (b - MB) * JB; woff = 3 * H; }
        #pragma unroll
        for (int jj = 0; jj < JB; jj++) xs[jj][t] = src[(r0 + jj) * H + t];
        __syncthreads();
        float acc[JB];
        #pragma unroll
        for (int jj = 0; jj < JB; jj++) acc[jj] = 0.f;
        const float* w = W0 + woff * H + t;
        #pragma unroll 8
        for (int i4 = 0; i4 < H / 4; i4++) {
            float w0 = w[(4 * i4 + 0) * H];
            float w1 = w[(4 * i4 + 1) * H];
            float w2 = w[(4 * i4 + 2) * H];
            float w3 = w[(4 * i4 + 3) * H];
            #pragma unroll
            for (int jj = 0; jj < JB; jj++) {
                float4 x = *(const float4*)&xs[jj][4 * i4];
                acc[jj] += x.x * w0 + x.y * w1 + x.z * w2 + x.w * w3;
            }
        }
        #pragma unroll
        for (int jj = 0; jj < JB; jj++) dst[(r0 + jj) * H + t] = acc[jj];
    } else {
        __shared__ float x2[2 * H];
        x2[t] = xg[t];
        x2[t + H] = xg[t + H];
        __syncthreads();
        float acc = b0[t];
        const float* w = W0 + t;
        #pragma unroll 8
        for (int i = 0; i < 2 * H; i++) acc += x2[i] * w[i * H];
        g_c[t] = acc;
    }
}

// ---------------- K2: fused score + online softmax ----------------
// W1 packed along reduction dim (u64 pairs) in smem. Per-warp DOUBLE-BUFFERED
// h staging: next pass's gather/relu/store is issued before the current pass's
// epilogue so the LDG chain hides under epilogue compute. Epilogue reduces all
// RPW rows with ILP-batched butterflies and a single batched softmax update.
__global__ void __launch_bounds__(512, 1) score_kernel(
        const int*   __restrict__ m_ids,
        const int*   __restrict__ job_idx,
        const float* __restrict__ W1,
        const float* __restrict__ b1,
        const float* __restrict__ W2,
        const float* __restrict__ b2) {
    extern __shared__ float smem[];
    u64*   W1p  = (u64*)smem;                  // [64][128] u64 = 64KB
    float* hstg = smem + 2 * 64 * H;           // 16 warps * 2 bufs * RPW*H = 128KB

    int tid  = threadIdx.x;
    int lane = tid & 31;
    int wid  = tid >> 5;

    for (int idx = tid; idx < 64 * H; idx += 512) {
        int i2 = idx >> 7, c = idx & (H - 1);
        W1p[idx] = pack2(W1[(2 * i2) * H + c], W1[(2 * i2 + 1) * H + c]);
    }

    float4 creg  = ((const float4*)g_c)[lane];
    float4 b1reg = ((const float4*)b1)[lane];
    float4 w2reg = ((const float4*)W2)[lane];
    float  b2v   = b2[0];
    __syncthreads();

    float* wh = hstg + wid * (2 * RPW * H);    // this warp's two buffers
    const float4* A4 = (const float4*)g_A;
    const float4* B4 = (const float4*)g_B;

    float mx = -3.402823466e38f, Z = 0.f, S1 = 0.f;
    int   arg = 0x7fffffff;

    int gw = blockIdx.x * SWARPS + wid;
    const int stride = SBLOCKS * SWARPS * RPW;

    // stage helper (lambda-free, inlined manually below via macro-ish loop)
    #define STAGE(BUFP, BASEP)                                               \
    do {                                                                     \
        float* hb = wh + (BUFP) * (RPW * H);                                 \
        _Pragma("unroll")                                                    \
        for (int r = 0; r < RPW; r++) {                                      \
            int m = m_ids[(BASEP) + r];                                      \
            int j = job_idx[(BASEP) + r];                                    \
            float4 a  = A4[m * (H / 4) + lane];                              \
            float4 bb = B4[j * (H / 4) + lane];                              \
            float4 h;                                                        \
            h.x = fmaxf(creg.x + a.x + bb.x, 0.f);                           \
            h.y = fmaxf(creg.y + a.y + bb.y, 0.f);                           \
            h.z = fmaxf(creg.z + a.z + bb.z, 0.f);                           \
            h.w = fmaxf(creg.w + a.w + bb.w, 0.f);                           \
            ((float4*)(hb + r * H))[lane] = h;                               \
        }                                                                    \
    } while (0)

    int base = gw * RPW;
    bool valid = (base + RPW <= NROWS);
    int buf = 0;
    if (valid) { STAGE(0, base); }
    __syncwarp();

    while (valid) {
        int  nbase  = base + stride;
        bool nvalid = (nbase + RPW <= NROWS);

        // ---- mainloop: layer 2 on packed-reduction f32x2 ----
        const float* myh = wh + buf * (RPW * H);
        u64 acc[RPW][4];
        #pragma unroll
        for (int r = 0; r < RPW; r++)
            acc[r][0] = acc[r][1] = acc[r][2] = acc[r][3] = 0ull;

        #pragma unroll 4
        for (int iq = 0; iq < H / 4; iq++) {
            const u64* wrowA = W1p + (2 * iq)     * H + 4 * lane;
            const u64* wrowB = W1p + (2 * iq + 1) * H + 4 * lane;
            ulonglong2 wA0 = *(const ulonglong2*)(wrowA);
            ulonglong2 wA1 = *(const ulonglong2*)(wrowA + 2);
            ulonglong2 wB0 = *(const ulonglong2*)(wrowB);
            ulonglong2 wB1 = *(const ulonglong2*)(wrowB + 2);
            #pragma unroll
            for (int r = 0; r < RPW; r++) {
                ulonglong2 hp = *(const ulonglong2*)(myh + r * H + 4 * iq);
                acc[r][0] = ffma2(hp.x, wA0.x, acc[r][0]);
                acc[r][1] = ffma2(hp.x, wA0.y, acc[r][1]);
                acc[r][2] = ffma2(hp.x, wA1.x, acc[r][2]);
                acc[r][3] = ffma2(hp.x, wA1.y, acc[r][3]);
                acc[r][0] = ffma2(hp.y, wB0.x, acc[r][0]);
                acc[r][1] = ffma2(hp.y, wB0.y, acc[r][1]);
                acc[r][2] = ffma2(hp.y, wB1.x, acc[r][2]);
                acc[r][3] = ffma2(hp.y, wB1.y, acc[r][3]);
            }
        }

        // ---- stage NEXT pass now: LDG chain hides under epilogue ----
        if (nvalid) { STAGE(buf ^ 1, nbase); }

        // ---- batched epilogue: layer 3, ILP shuffles, batched softmax ----
        float s[RPW];
        #pragma unroll
        for (int r = 0; r < RPW; r++) {
            float2 p0 = unpack2(acc[r][0]);
            float2 p1 = unpack2(acc[r][1]);
            float2 p2 = unpack2(acc[r][2]);
            float2 p3 = unpack2(acc[r][3]);
            float h0 = p0.x + p0.y + b1reg.x;
            float h1 = p1.x + p1.y + b1reg.y;
            float h2 = p2.x + p2.y + b1reg.z;
            float h3 = p3.x + p3.y + b1reg.w;
            s[r] = fmaxf(h0, 0.f) * w2reg.x + fmaxf(h1, 0.f) * w2reg.y
                 + fmaxf(h2, 0.f) * w2reg.z + fmaxf(h3, 0.f) * w2reg.w;
        }
        #pragma unroll
        for (int off = 16; off; off >>= 1) {
            #pragma unroll
            for (int r = 0; r < RPW; r++)
                s[r] += __shfl_xor_sync(0xffffffffu, s[r], off);
        }
        #pragma unroll
        for (int r = 0; r < RPW; r++) s[r] += b2v;

        float bmax = s[0]; int barg = 0;
        #pragma unroll
        for (int r = 1; r < RPW; r++)
            if (s[r] > bmax) { bmax = s[r]; barg = r; }

        if (bmax > mx) {
            float d = fmaxf(mx - bmax, -87.f);
            float e = expf(d);
            S1 = e * (S1 + d * Z);
            Z  = e * Z;
            mx = bmax;
            arg = base + barg;
        }
        float zadd = 0.f, sadd = 0.f;
        #pragma unroll
        for (int r = 0; r < RPW; r++) {
            float t = fmaxf(s[r] - mx, -87.f);
            float e = expf(t);
            zadd += e;
            sadd += t * e;
        }
        Z  += zadd;
        S1 += sadd;

        base = nbase; valid = nvalid; buf ^= 1;
        __syncwarp();
    }
    #undef STAGE

    if (lane == 0) {
        g_wmax[gw] = mx;
        g_warg[gw] = arg;
        g_wZ[gw]   = Z;
        g_wS1[gw]  = S1;
    }
}

// ---------------- K3: merge warp partials, write outputs ----------------
__global__ void finalize_kernel(float* __restrict__ out) {
    __shared__ float smx[256], sZ[256], sS1[256];
    __shared__ int   sarg[256];
    int tid = threadIdx.x;

    float mx = -3.402823466e38f, Z = 0.f, S1 = 0.f;
    int   arg = 0x7fffffff;

    for (int i = tid; i < NWTOT; i += 256) {
        float qm = g_wmax[i], qZ = g_wZ[i], qS = g_wS1[i];
        int   qa = g_warg[i];
        if (qm > mx || (qm == mx && qa < arg)) {
            float d = fmaxf(mx - qm, -87.f);
            float e = expf(d);
            float Zo = Z, S1o = S1;
            Z  = qZ + e * Zo;
            S1 = qS + e * (S1o + d * Zo);
            mx = qm; arg = qa;
        } else {
            float d = fmaxf(qm - mx, -87.f);
            float e = expf(d);
            Z  += e * qZ;
            S1 += e * (qS + d * qZ);
        }
    }
    smx[tid] = mx; sarg[tid] = arg; sZ[tid] = Z; sS1[tid] = S1;
    __syncthreads();

    for (int s = 128; s; s >>= 1) {
        if (tid < s) {
            float qm = smx[tid + s], qZ = sZ[tid + s], qS = sS1[tid + s];
            int   qa = sarg[tid + s];
            if (qm > smx[tid] || (qm == smx[tid] && qa < sarg[tid])) {
                float d = fmaxf(smx[tid] - qm, -87.f);
                float e = expf(d);
                float Zo = sZ[tid], S1o = sS1[tid];
                sZ[tid]  = qZ + e * Zo;
                sS1[tid] = qS + e * (S1o + d * Zo);
                smx[tid] = qm; sarg[tid] = qa;
            } else {
                float d = fmaxf(qm - smx[tid], -87.f);
                float e = expf(d);
                sZ[tid]  += e * qZ;
                sS1[tid] += e * (qS + d * qZ);
            }
        }
        __syncthreads();
    }

    if (tid == 0) {
        float Zf   = sZ[0];
        float S1f  = sS1[0];
        float logZ = logf(Zf);
        out[0] = (float)sarg[0];
        out[1] = 1.0f / Zf;
        out[2] = -logZ;
        out[3] = logZ - S1f / Zf;
    }
}

// ---------------- launch ----------------
extern "C" void kernel_launch(void* const* d_in, const int* in_sizes, int n_in,
                              void* d_out, int out_size) {
    const float* x_graph = (const float*)d_in[0];
    const float* x_m     = (const float*)d_in[1];
    const float* x_job   = (const float*)d_in[2];
    const int*   m_ids   = (const int*)  d_in[3];
    const int*   job_idx = (const int*)  d_in[4];
    const float* W0      = (const float*)d_in[5];
    const float* b0      = (const float*)d_in[6];
    const float* W1      = (const float*)d_in[7];
    const float* b1      = (const float*)d_in[8];
    const float* W2      = (const float*)d_in[9];
    const float* b2      = (const float*)d_in[10];
    float* out = (float*)d_out;

    const int smem_bytes = 64 * H * 8 + SWARPS * 2 * RPW * H * 4; // 64KB+128KB
    cudaFuncSetAttribute(score_kernel,
                         cudaFuncAttributeMaxDynamicSharedMemorySize, smem_bytes);

    precompute_kernel<<<M_NODES / JB + J_NODES / JB + 1, H>>>(x_graph, x_m, x_job, W0, b0);
    score_kernel<<<SBLOCKS, 512, smem_bytes>>>(m_ids, job_idx, W1, b1, W2, b2);
    finalize_kernel<<<1, 256>>>(out);
}

// round 7
// speedup vs baseline: 1.6803x; 1.6803x over previous
#include <cuda_runtime.h>
#include <cuda_bf16.h>
#include <cstdint>

#define H        128
#define NROWS    200000
#define NTILES   ((NROWS + 127) / 128)   // 1563
#define M_NODES  1000
#define J_NODES  5000
#define SBLOCKS  296                     // 2 blocks/SM
#define NWTOT    SBLOCKS

// staged-h row stride in bytes: 272 = 16*17 -> 16B-aligned ldmatrix rows,
// per-row bank shift = 68 mod 32 = 4 -> 8 rows hit 8 distinct 4-bank groups.
#define HSB       272
#define HS_LO_OFF (128 * HSB)            // 34816
#define PART_OFF  (2 * 128 * HSB)        // 69632
#define CS_OFF    (PART_OFF + 4096)      // 73728
#define SMEM_SZ   (CS_OFF + 512)         // 74240

// ---------------- device scratch ----------------
__device__ __align__(16) float g_c[H];
__device__ __align__(16) float g_A[M_NODES * H];
__device__ __align__(16) float g_B[J_NODES * H];
__device__ float g_wmax[NWTOT];
__device__ int   g_warg[NWTOT];
__device__ float g_wZ[NWTOT];
__device__ float g_wS1[NWTOT];

// ---------------- PTX helpers (generic ISA only — no 'a' features) ----------
__device__ __forceinline__ uint32_t smem_u32(const void* p) {
    uint32_t a;
    asm("{ .reg .u64 t; cvta.to.shared.u64 t, %1; cvt.u32.u64 %0, t; }" : "=r"(a) : "l"(p));
    return a;
}
__device__ __forceinline__ void ldsm_x4(uint32_t* r, uint32_t addr) {
    asm volatile("ldmatrix.sync.aligned.m8n8.x4.shared.b16 {%0,%1,%2,%3}, [%4];"
        : "=r"(r[0]), "=r"(r[1]), "=r"(r[2]), "=r"(r[3]) : "r"(addr));
}
__device__ __forceinline__ void mma_bf16(float* d, const uint32_t* a, const uint32_t* b) {
    asm volatile("mma.sync.aligned.m16n8k16.row.col.f32.bf16.bf16.f32 "
        "{%0,%1,%2,%3}, {%4,%5,%6,%7}, {%8,%9}, {%0,%1,%2,%3};"
        : "+f"(d[0]), "+f"(d[1]), "+f"(d[2]), "+f"(d[3])
        : "r"(a[0]), "r"(a[1]), "r"(a[2]), "r"(a[3]), "r"(b[0]), "r"(b[1]));
}
__device__ __forceinline__ uint32_t pack_bf2(float lo, float hi) {
    __nv_bfloat162 t;
    t.x = __float2bfloat16_rn(lo);
    t.y = __float2bfloat16_rn(hi);
    return *(uint32_t*)&t;
}

// ---------------- K1: precompute cg, A, B ----------------
__global__ void __launch_bounds__(256) precompute_kernel(
        const float* __restrict__ xg, const float* __restrict__ xm,
        const float* __restrict__ xj, const float* __restrict__ W0,
        const float* __restrict__ b0) {
    const int MB  = (M_NODES + 15) / 16;   // 63
    const int JBL = (J_NODES + 15) / 16;   // 313
    int b = blockIdx.x, tid = threadIdx.x;
    int t = tid & 127, half = tid >> 7;
    __shared__ __align__(16) float xs[16][H];
    __shared__ float x2[2 * H];

    if (b < MB + JBL) {
        const float* src; float* dst; int r0, cnt, woff;
        if (b < MB) { src = xm; dst = g_A; r0 = b * 16;        cnt = M_NODES; woff = 2 * H; }
        else        { src = xj; dst = g_B; r0 = (b - MB) * 16; cnt = J_NODES; woff = 3 * H; }
        for (int i = tid; i < 16 * H; i += 256) {
            int r = r0 + (i >> 7); if (r >= cnt) r = cnt - 1;
            xs[i >> 7][i & 127] = src[r * H + (i & 127)];
        }
        __syncthreads();
        float acc[8];
        #pragma unroll
        for (int jj = 0; jj < 8; jj++) acc[jj] = 0.f;
        const float* w = W0 + woff * H + t;
        #pragma unroll 8
        for (int i4 = 0; i4 < H / 4; i4++) {
            float w0 = w[(4 * i4 + 0) * H], w1 = w[(4 * i4 + 1) * H];
            float w2 = w[(4 * i4 + 2) * H], w3 = w[(4 * i4 + 3) * H];
            #pragma unroll
            for (int jj = 0; jj < 8; jj++) {
                float4 x = *(const float4*)&xs[half * 8 + jj][4 * i4];
                acc[jj] += x.x * w0 + x.y * w1 + x.z * w2 + x.w * w3;
            }
        }
        #pragma unroll
        for (int jj = 0; jj < 8; jj++) {
            int r = r0 + half * 8 + jj;
            if (r < cnt) dst[r * H + t] = acc[jj];
        }
    } else {
        x2[tid] = xg[tid];                 // 256 = 2H exactly
        __syncthreads();
        if (half == 0) {
            float acc = b0[t];
            const float* w = W0 + t;
            #pragma unroll 8
            for (int i = 0; i < 2 * H; i++) acc += x2[i] * w[i * H];
            g_c[t] = acc;
        }
    }
}

// ---------------- K2: bf16-split HMMA score kernel ----------------
// Per tile (128 rows): h gathered fp32, split into bf16 hi/lo, staged in smem.
// Warp w owns outcols 16w..16w+15 (2 n-tiles); W1 frags (hi/lo) in registers.
// D = Ahi*Bhi + Ahi*Blo + Alo*Bhi accumulated fp32 by mma.m16n8k16.
__global__ void __launch_bounds__(256, 2) score_kernel(
        const int*   __restrict__ m_ids, const int* __restrict__ job_idx,
        const float* __restrict__ W1,    const float* __restrict__ b1,
        const float* __restrict__ W2,    const float* __restrict__ b2) {
    extern __shared__ char smem[];
    uint32_t sbase = smem_u32(smem);
    float* part = (float*)(smem + PART_OFF);    // [8][128]
    float* cs   = (float*)(smem + CS_OFF);      // g_c copy

    int tid  = threadIdx.x;
    int lane = tid & 31;
    int wid  = tid >> 5;
    int g    = lane >> 2;        // 0..7
    int tig  = lane & 3;         // 0..3

    // ---- W1 fragments into registers (hi/lo), once ----
    uint32_t Bh[8][2][2], Bl[8][2][2];
    {
        int n = wid * 16 + g;    // + lnt*8
        #pragma unroll
        for (int kk = 0; kk < 8; kk++)
            #pragma unroll
            for (int lnt = 0; lnt < 2; lnt++)
                #pragma unroll
                for (int e = 0; e < 2; e++) {
                    int k0 = kk * 16 + 2 * tig + e * 8;
                    float wa = W1[k0 * H + n + lnt * 8];
                    float wb = W1[(k0 + 1) * H + n + lnt * 8];
                    float ha = __bfloat162float(__float2bfloat16_rn(wa));
                    float hb = __bfloat162float(__float2bfloat16_rn(wb));
                    Bh[kk][lnt][e] = pack_bf2(ha, hb);
                    Bl[kk][lnt][e] = pack_bf2(wa - ha, wb - hb);
                }
    }
    // per-thread output-column constants
    float b1c[2][2], w2c[2][2];
    #pragma unroll
    for (int lnt = 0; lnt < 2; lnt++)
        #pragma unroll
        for (int e = 0; e < 2; e++) {
            int col = wid * 16 + lnt * 8 + 2 * tig + e;
            b1c[lnt][e] = b1[col];
            w2c[lnt][e] = W2[col];
        }
    float b2v = b2[0];
    if (tid < H) cs[tid] = g_c[tid];
    __syncthreads();

    const float4* A4 = (const float4*)g_A;
    const float4* B4 = (const float4*)g_B;
    const float4* C4 = (const float4*)cs;

    // ldmatrix per-lane address offset (rows within m-tile, col-halves)
    uint32_t laneoff = (uint32_t)(((lane & 7) + ((lane >> 3) & 1) * 8) * HSB
                                  + ((lane >> 4) & 1) * 16);

    float mx = -3.402823466e38f, Z = 0.f, S1 = 0.f;
    int   arg = 0x7fffffff;

    for (int tile = blockIdx.x; tile < NTILES; tile += SBLOCKS) {
        int tbase = tile * 128;

        // ---- gather + bf16 hi/lo staging (threads 0..127, one row each) ----
        if (tid < 128) {
            char* rh = smem + tid * HSB;
            char* rl = rh + HS_LO_OFF;
            int grow = tbase + tid;
            if (grow < NROWS) {
                int m = m_ids[grow], j = job_idx[grow];
                const float4* Am = A4 + m * 32;
                const float4* Bj = B4 + j * 32;
                #pragma unroll 8
                for (int c = 0; c < 32; c++) {
                    float4 a = Am[c], bb = Bj[c], cc = C4[c];
                    float hx = fmaxf(cc.x + a.x + bb.x, 0.f);
                    float hy = fmaxf(cc.y + a.y + bb.y, 0.f);
                    float hz = fmaxf(cc.z + a.z + bb.z, 0.f);
                    float hw = fmaxf(cc.w + a.w + bb.w, 0.f);
                    float ix = __bfloat162float(__float2bfloat16_rn(hx));
                    float iy = __bfloat162float(__float2bfloat16_rn(hy));
                    float iz = __bfloat162float(__float2bfloat16_rn(hz));
                    float iw = __bfloat162float(__float2bfloat16_rn(hw));
                    uint2 hv, lv;
                    hv.x = pack_bf2(ix, iy);
                    hv.y = pack_bf2(iz, iw);
                    lv.x = pack_bf2(hx - ix, hy - iy);
                    lv.y = pack_bf2(hz - iz, hw - iw);
                    *(uint2*)(rh + 8 * c) = hv;
                    *(uint2*)(rl + 8 * c) = lv;
                }
            } else {
                uint2 zz = make_uint2(0u, 0u);
                #pragma unroll 8
                for (int c = 0; c < 32; c++) {
                    *(uint2*)(rh + 8 * c) = zz;
                    *(uint2*)(rl + 8 * c) = zz;
                }
            }
        }
        __syncthreads();

        // ---- mainloop: 8 m-tiles x 8 k-steps x (2 nt x 3 products) ----
        #pragma unroll 1
        for (int mt = 0; mt < 8; mt++) {
            float d0[4] = {0.f, 0.f, 0.f, 0.f};
            float d1[4] = {0.f, 0.f, 0.f, 0.f};
            uint32_t ahi = sbase + (uint32_t)(mt * 16 * HSB) + laneoff;
            uint32_t alo = ahi + HS_LO_OFF;
            #pragma unroll
            for (int kk = 0; kk < 8; kk++) {
                uint32_t ah[4], al[4];
                ldsm_x4(ah, ahi + kk * 32);
                ldsm_x4(al, alo + kk * 32);
                mma_bf16(d0, ah, Bh[kk][0]);
                mma_bf16(d1, ah, Bh[kk][1]);
                mma_bf16(d0, ah, Bl[kk][0]);
                mma_bf16(d1, ah, Bl[kk][1]);
                mma_bf16(d0, al, Bh[kk][0]);
                mma_bf16(d1, al, Bh[kk][1]);
            }
            // rows g / g+8 partial over this warp's 16 outcols
            float sg = fmaxf(d0[0] + b1c[0][0], 0.f) * w2c[0][0]
                     + fmaxf(d0[1] + b1c[0][1], 0.f) * w2c[0][1]
                     + fmaxf(d1[0] + b1c[1][0], 0.f) * w2c[1][0]
                     + fmaxf(d1[1] + b1c[1][1], 0.f) * w2c[1][1];
            float sh = fmaxf(d0[2] + b1c[0][0], 0.f) * w2c[0][0]
                     + fmaxf(d0[3] + b1c[0][1], 0.f) * w2c[0][1]
                     + fmaxf(d1[2] + b1c[1][0], 0.f) * w2c[1][0]
                     + fmaxf(d1[3] + b1c[1][1], 0.f) * w2c[1][1];
            sg += __shfl_xor_sync(0xffffffffu, sg, 1);
            sg += __shfl_xor_sync(0xffffffffu, sg, 2);
            sh += __shfl_xor_sync(0xffffffffu, sh, 1);
            sh += __shfl_xor_sync(0xffffffffu, sh, 2);
            if (tig == 0) {
                part[wid * 128 + mt * 16 + g]     = sg;
                part[wid * 128 + mt * 16 + 8 + g] = sh;
            }
        }
        __syncthreads();

        // ---- per-row score + online softmax (threads 0..127) ----
        if (tid < 128) {
            int grow = tbase + tid;
            if (grow < NROWS) {
                float s = b2v;
                #pragma unroll
                for (int w = 0; w < 8; w++) s += part[w * 128 + tid];
                if (s > mx) {
                    float dd = fmaxf(mx - s, -87.f);
                    float e = expf(dd);
                    S1 = e * (S1 + dd * Z);
                    Z  = e * Z + 1.f;
                    mx = s;
                    arg = grow;
                } else {
                    float t = fmaxf(s - mx, -87.f);
                    float e = expf(t);
                    Z  += e;
                    S1 += t * e;
                }
            }
        }
        __syncthreads();
    }

    // ---- block merge of per-thread softmax states (reuse part: 4KB) ----
    float* smx = part;
    float* sZ  = part + 256;
    float* sS1 = part + 512;
    int*   sarg = (int*)(part + 768);
    smx[tid] = mx; sZ[tid] = Z; sS1[tid] = S1; sarg[tid] = arg;
    __syncthreads();
    for (int s = 128; s; s >>= 1) {
        if (tid < s) {
            float qm = smx[tid + s], qZ = sZ[tid + s], qS = sS1[tid + s];
            int   qa = sarg[tid + s];
            if (qm > smx[tid] || (qm == smx[tid] && qa < sarg[tid])) {
                float d = fmaxf(smx[tid] - qm, -87.f);
                float e = expf(d);
                float Zo = sZ[tid], S1o = sS1[tid];
                sZ[tid]  = qZ + e * Zo;
                sS1[tid] = qS + e * (S1o + d * Zo);
                smx[tid] = qm; sarg[tid] = qa;
            } else {
                float d = fmaxf(qm - smx[tid], -87.f);
                float e = expf(d);
                sZ[tid]  += e * qZ;
                sS1[tid] += e * (qS + d * qZ);
            }
        }
        __syncthreads();
    }
    if (tid == 0) {
        g_wmax[blockIdx.x] = smx[0];
        g_warg[blockIdx.x] = sarg[0];
        g_wZ[blockIdx.x]   = sZ[0];
        g_wS1[blockIdx.x]  = sS1[0];
    }
}

// ---------------- K3: merge 296 block partials ----------------
__global__ void __launch_bounds__(512) finalize_kernel(float* __restrict__ out) {
    __shared__ float smx[512], sZ[512], sS1[512];
    __shared__ int   sarg[512];
    int tid = threadIdx.x;

    float mx = -3.402823466e38f, Z = 0.f, S1 = 0.f;
    int   arg = 0x7fffffff;
    if (tid < NWTOT) { mx = g_wmax[tid]; Z = g_wZ[tid]; S1 = g_wS1[tid]; arg = g_warg[tid]; }
    smx[tid] = mx; sarg[tid] = arg; sZ[tid] = Z; sS1[tid] = S1;
    __syncthreads();

    for (int s = 256; s; s >>= 1) {
        if (tid < s) {
            float qm = smx[tid + s], qZ = sZ[tid + s], qS = sS1[tid + s];
            int   qa = sarg[tid + s];
            if (qm > smx[tid] || (qm == smx[tid] && qa < sarg[tid])) {
                float d = fmaxf(smx[tid] - qm, -87.f);
                float e = expf(d);
                float Zo = sZ[tid], S1o = sS1[tid];
                sZ[tid]  = qZ + e * Zo;
                sS1[tid] = qS + e * (S1o + d * Zo);
                smx[tid] = qm; sarg[tid] = qa;
            } else {
                float d = fmaxf(qm - smx[tid], -87.f);
                float e = expf(d);
                sZ[tid]  += e * qZ;
                sS1[tid] += e * (qS + d * qZ);
            }
        }
        __syncthreads();
    }

    if (tid == 0) {
        float Zf = sZ[0], S1f = sS1[0];
        float logZ = logf(Zf);
        out[0] = (float)sarg[0];
        out[1] = 1.0f / Zf;          // p[idx]  (t=0 at argmax)
        out[2] = -logZ;              // logp[idx]
        out[3] = logZ - S1f / Zf;    // entropy
    }
}

// ---------------- launch ----------------
extern "C" void kernel_launch(void* const* d_in, const int* in_sizes, int n_in,
                              void* d_out, int out_size) {
    const float* x_graph = (const float*)d_in[0];
    const float* x_m     = (const float*)d_in[1];
    const float* x_job   = (const float*)d_in[2];
    const int*   m_ids   = (const int*)  d_in[3];
    const int*   job_idx = (const int*)  d_in[4];
    const float* W0      = (const float*)d_in[5];
    const float* b0      = (const float*)d_in[6];
    const float* W1      = (const float*)d_in[7];
    const float* b1      = (const float*)d_in[8];
    const float* W2      = (const float*)d_in[9];
    const float* b2      = (const float*)d_in[10];
    float* out = (float*)d_out;

    cudaFuncSetAttribute(score_kernel,
                         cudaFuncAttributeMaxDynamicSharedMemorySize, SMEM_SZ);

    const int MB  = (M_NODES + 15) / 16;
    const int JBL = (J_NODES + 15) / 16;
    precompute_kernel<<<MB + JBL + 1, 256>>>(x_graph, x_m, x_job, W0, b0);
    score_kernel<<<SBLOCKS, 256, SMEM_SZ>>>(m_ids, job_idx, W1, b1, W2, b2);
    finalize_kernel<<<1, 512>>>(out);
}

// round 9
// speedup vs baseline: 2.1035x; 1.2519x over previous
#include <cuda_runtime.h>
#include <cuda_bf16.h>
#include <cuda_fp16.h>
#include <cstdint>

#define H        128
#define NROWS    200000
#define NTILES   ((NROWS + 127) / 128)   // 1563
#define M_NODES  1000
#define J_NODES  5000
#define SBLOCKS  296                     // 2 blocks/SM
#define NWTOT    SBLOCKS

// staged row stride in bytes: 272 = 16*17 -> 16B-aligned ldmatrix rows,
// per-row bank shift = 68 mod 32 = 4 -> conflict-free 8x8 matrices.
#define HSB       272

// score kernel smem (hi buffer only, fp16)
#define PART_OFF  (128 * HSB)            // 34816
#define CS_OFF    (PART_OFF + 4096)      // 38912
#define SMEM_SZ   (CS_OFF + 512)         // 39424

// precompute kernel smem (hi + lo bf16, 64 rows)
#define P_LO_OFF  (64 * HSB)             // 17408
#define P_SMEM    (2 * 64 * HSB)         // 34816
#define NT_M      16                     // ceil(1000/64)
#define NT_J      79                     // ceil(5000/64)

// ---------------- device scratch ----------------
__device__ __align__(16) float g_c[H];
__device__ __align__(16) float g_A[M_NODES * H];
__device__ __align__(16) float g_B[J_NODES * H];
__device__ float g_wmax[NWTOT];
__device__ int   g_warg[NWTOT];
__device__ float g_wZ[NWTOT];
__device__ float g_wS1[NWTOT];

// ---------------- PTX helpers (generic ISA only) ----------------
__device__ __forceinline__ uint32_t smem_u32(const void* p) {
    uint32_t a;
    asm("{ .reg .u64 t; cvta.to.shared.u64 t, %1; cvt.u32.u64 %0, t; }" : "=r"(a) : "l"(p));
    return a;
}
__device__ __forceinline__ void ldsm_x4(uint32_t* r, uint32_t addr) {
    asm volatile("ldmatrix.sync.aligned.m8n8.x4.shared.b16 {%0,%1,%2,%3}, [%4];"
        : "=r"(r[0]), "=r"(r[1]), "=r"(r[2]), "=r"(r[3]) : "r"(addr));
}
__device__ __forceinline__ void mma_bf16(float* d, const uint32_t* a, const uint32_t* b) {
    asm volatile("mma.sync.aligned.m16n8k16.row.col.f32.bf16.bf16.f32 "
        "{%0,%1,%2,%3}, {%4,%5,%6,%7}, {%8,%9}, {%0,%1,%2,%3};"
        : "+f"(d[0]), "+f"(d[1]), "+f"(d[2]), "+f"(d[3])
        : "r"(a[0]), "r"(a[1]), "r"(a[2]), "r"(a[3]), "r"(b[0]), "r"(b[1]));
}
__device__ __forceinline__ void mma_f16(float* d, const uint32_t* a, const uint32_t* b) {
    asm volatile("mma.sync.aligned.m16n8k16.row.col.f32.f16.f16.f32 "
        "{%0,%1,%2,%3}, {%4,%5,%6,%7}, {%8,%9}, {%0,%1,%2,%3};"
        : "+f"(d[0]), "+f"(d[1]), "+f"(d[2]), "+f"(d[3])
        : "r"(a[0]), "r"(a[1]), "r"(a[2]), "r"(a[3]), "r"(b[0]), "r"(b[1]));
}
__device__ __forceinline__ uint32_t pack_bf2(float lo, float hi) {
    __nv_bfloat162 t;
    t.x = __float2bfloat16_rn(lo);
    t.y = __float2bfloat16_rn(hi);
    return *(uint32_t*)&t;
}
__device__ __forceinline__ uint32_t pack_h2(float lo, float hi) {
    __half2 t = __floats2half2_rn(lo, hi);
    return *(uint32_t*)&t;
}

// ---------------- K1: precompute via bf16 3-product HMMA ----------------
// Tile = 64 rows. Block b < NT_M: machines -> g_A (W0[2H..3H]);
// else jobs -> g_B (W0[3H..4H]); last block computes g_c in fp32.
__global__ void __launch_bounds__(256, 2) precompute_kernel(
        const float* __restrict__ xg, const float* __restrict__ xm,
        const float* __restrict__ xj, const float* __restrict__ W0,
        const float* __restrict__ b0) {
    extern __shared__ char smem[];
    __shared__ float x2[2 * H];
    int b = blockIdx.x, tid = threadIdx.x;

    if (b == NT_M + NT_J) {
        // graph constant (fp32, exact)
        x2[tid] = xg[tid];
        __syncthreads();
        if (tid < H) {
            float acc = b0[tid];
            const float* w = W0 + tid;
            #pragma unroll 8
            for (int i = 0; i < 2 * H; i++) acc += x2[i] * w[i * H];
            g_c[tid] = acc;
        }
        return;
    }

    const float* src; float* dst; int r0, cnt, woff;
    if (b < NT_M) { src = xm; dst = g_A; r0 = b * 64;          cnt = M_NODES; woff = 2 * H; }
    else          { src = xj; dst = g_B; r0 = (b - NT_M) * 64; cnt = J_NODES; woff = 3 * H; }

    uint32_t sbase = smem_u32(smem);
    int lane = tid & 31, wid = tid >> 5;
    int g = lane >> 2, tig = lane & 3;

    // W0 fragments hi/lo (this warp's 16 outcols)
    uint32_t Bh[8][2][2], Bl[8][2][2];
    {
        int n = wid * 16 + g;
        #pragma unroll
        for (int kk = 0; kk < 8; kk++)
            #pragma unroll
            for (int lnt = 0; lnt < 2; lnt++)
                #pragma unroll
                for (int e = 0; e < 2; e++) {
                    int k0 = kk * 16 + 2 * tig + e * 8;
                    float wa = W0[(woff + k0) * H + n + lnt * 8];
                    float wb = W0[(woff + k0 + 1) * H + n + lnt * 8];
                    float ha = __bfloat162float(__float2bfloat16_rn(wa));
                    float hb = __bfloat162float(__float2bfloat16_rn(wb));
                    Bh[kk][lnt][e] = pack_bf2(ha, hb);
                    Bl[kk][lnt][e] = pack_bf2(wa - ha, wb - hb);
                }
    }

    // stage 64 x-rows (hi/lo bf16)
    if (tid < 64) {
        char* rh = smem + tid * HSB;
        char* rl = rh + P_LO_OFF;
        int r = r0 + tid;
        if (r < cnt) {
            const float4* xr = (const float4*)(src + r * H);
            #pragma unroll 8
            for (int c = 0; c < 32; c++) {
                float4 x = xr[c];
                float ix = __bfloat162float(__float2bfloat16_rn(x.x));
                float iy = __bfloat162float(__float2bfloat16_rn(x.y));
                float iz = __bfloat162float(__float2bfloat16_rn(x.z));
                float iw = __bfloat162float(__float2bfloat16_rn(x.w));
                uint2 hv, lv;
                hv.x = pack_bf2(ix, iy);
                hv.y = pack_bf2(iz, iw);
                lv.x = pack_bf2(x.x - ix, x.y - iy);
                lv.y = pack_bf2(x.z - iz, x.w - iw);
                *(uint2*)(rh + 8 * c) = hv;
                *(uint2*)(rl + 8 * c) = lv;
            }
        } else {
            uint2 zz = make_uint2(0u, 0u);
            #pragma unroll 8
            for (int c = 0; c < 32; c++) {
                *(uint2*)(rh + 8 * c) = zz;
                *(uint2*)(rl + 8 * c) = zz;
            }
        }
    }
    __syncthreads();

    uint32_t laneoff = (uint32_t)(((lane & 7) + ((lane >> 3) & 1) * 8) * HSB
                                  + ((lane >> 4) & 1) * 16);

    #pragma unroll 1
    for (int mt = 0; mt < 4; mt++) {
        float d0[4] = {0.f, 0.f, 0.f, 0.f};
        float d1[4] = {0.f, 0.f, 0.f, 0.f};
        uint32_t ahi = sbase + (uint32_t)(mt * 16 * HSB) + laneoff;
        uint32_t alo = ahi + P_LO_OFF;
        #pragma unroll
        for (int kk = 0; kk < 8; kk++) {
            uint32_t ah[4], al[4];
            ldsm_x4(ah, ahi + kk * 32);
            ldsm_x4(al, alo + kk * 32);
            mma_bf16(d0, ah, Bh[kk][0]);
            mma_bf16(d1, ah, Bh[kk][1]);
            mma_bf16(d0, ah, Bl[kk][0]);
            mma_bf16(d1, ah, Bl[kk][1]);
            mma_bf16(d0, al, Bh[kk][0]);
            mma_bf16(d1, al, Bh[kk][1]);
        }
        int row0 = r0 + mt * 16 + g;
        int row1 = row0 + 8;
        int c0 = wid * 16 + 2 * tig;
        if (row0 < cnt) {
            *(float2*)&dst[row0 * H + c0]     = make_float2(d0[0], d0[1]);
            *(float2*)&dst[row0 * H + c0 + 8] = make_float2(d1[0], d1[1]);
        }
        if (row1 < cnt) {
            *(float2*)&dst[row1 * H + c0]     = make_float2(d0[2], d0[3]);
            *(float2*)&dst[row1 * H + c0 + 8] = make_float2(d1[2], d1[3]);
        }
    }
}

// ---------------- K2: fp16 single-product HMMA score kernel ----------------
__global__ void __launch_bounds__(256, 2) score_kernel(
        const int*   __restrict__ m_ids, const int* __restrict__ job_idx,
        const float* __restrict__ W1,    const float* __restrict__ b1,
        const float* __restrict__ W2,    const float* __restrict__ b2) {
    extern __shared__ char smem[];
    uint32_t sbase = smem_u32(smem);
    float* part = (float*)(smem + PART_OFF);    // [8][128]
    float* cs   = (float*)(smem + CS_OFF);      // g_c copy

    int tid  = threadIdx.x;
    int lane = tid & 31;
    int wid  = tid >> 5;
    int g    = lane >> 2;
    int tig  = lane & 3;

    // W1 fragments (fp16), once
    uint32_t Fh[8][2][2];
    {
        int n = wid * 16 + g;
        #pragma unroll
        for (int kk = 0; kk < 8; kk++)
            #pragma unroll
            for (int lnt = 0; lnt < 2; lnt++)
                #pragma unroll
                for (int e = 0; e < 2; e++) {
                    int k0 = kk * 16 + 2 * tig + e * 8;
                    Fh[kk][lnt][e] = pack_h2(W1[k0 * H + n + lnt * 8],
                                             W1[(k0 + 1) * H + n + lnt * 8]);
                }
    }
    float b1c[2][2], w2c[2][2];
    #pragma unroll
    for (int lnt = 0; lnt < 2; lnt++)
        #pragma unroll
        for (int e = 0; e < 2; e++) {
            int col = wid * 16 + lnt * 8 + 2 * tig + e;
            b1c[lnt][e] = b1[col];
            w2c[lnt][e] = W2[col];
        }
    float b2v = b2[0];
    if (tid < H) cs[tid] = g_c[tid];
    __syncthreads();

    const float4* A4 = (const float4*)g_A;
    const float4* B4 = (const float4*)g_B;
    const float4* C4 = (const float4*)cs;

    uint32_t laneoff = (uint32_t)(((lane & 7) + ((lane >> 3) & 1) * 8) * HSB
                                  + ((lane >> 4) & 1) * 16);

    float mx = -3.402823466e38f, Z = 0.f, S1 = 0.f;
    int   arg = 0x7fffffff;

    for (int tile = blockIdx.x; tile < NTILES; tile += SBLOCKS) {
        int tbase = tile * 128;

        // gather + fp16 staging (threads 0..127, one row each)
        if (tid < 128) {
            char* rh = smem + tid * HSB;
            int grow = tbase + tid;
            if (grow < NROWS) {
                int m = m_ids[grow], j = job_idx[grow];
                const float4* Am = A4 + m * 32;
                const float4* Bj = B4 + j * 32;
                #pragma unroll 8
                for (int c = 0; c < 32; c++) {
                    float4 a = Am[c], bb = Bj[c], cc = C4[c];
                    float hx = fmaxf(cc.x + a.x + bb.x, 0.f);
                    float hy = fmaxf(cc.y + a.y + bb.y, 0.f);
                    float hz = fmaxf(cc.z + a.z + bb.z, 0.f);
                    float hw = fmaxf(cc.w + a.w + bb.w, 0.f);
                    uint2 hv;
                    hv.x = pack_h2(hx, hy);
                    hv.y = pack_h2(hz, hw);
                    *(uint2*)(rh + 8 * c) = hv;
                }
            } else {
                uint2 zz = make_uint2(0u, 0u);
                #pragma unroll 8
                for (int c = 0; c < 32; c++) *(uint2*)(rh + 8 * c) = zz;
            }
        }
        __syncthreads();

        // mainloop: 8 m-tiles x 8 k-steps x 2 n-tiles, single product
        #pragma unroll 1
        for (int mt = 0; mt < 8; mt++) {
            float d0[4] = {0.f, 0.f, 0.f, 0.f};
            float d1[4] = {0.f, 0.f, 0.f, 0.f};
            uint32_t ahi = sbase + (uint32_t)(mt * 16 * HSB) + laneoff;
            #pragma unroll
            for (int kk = 0; kk < 8; kk++) {
                uint32_t ah[4];
                ldsm_x4(ah, ahi + kk * 32);
                mma_f16(d0, ah, Fh[kk][0]);
                mma_f16(d1, ah, Fh[kk][1]);
            }
            float sg = fmaxf(d0[0] + b1c[0][0], 0.f) * w2c[0][0]
                     + fmaxf(d0[1] + b1c[0][1], 0.f) * w2c[0][1]
                     + fmaxf(d1[0] + b1c[1][0], 0.f) * w2c[1][0]
                     + fmaxf(d1[1] + b1c[1][1], 0.f) * w2c[1][1];
            float sh = fmaxf(d0[2] + b1c[0][0], 0.f) * w2c[0][0]
                     + fmaxf(d0[3] + b1c[0][1], 0.f) * w2c[0][1]
                     + fmaxf(d1[2] + b1c[1][0], 0.f) * w2c[1][0]
                     + fmaxf(d1[3] + b1c[1][1], 0.f) * w2c[1][1];
            sg += __shfl_xor_sync(0xffffffffu, sg, 1);
            sg += __shfl_xor_sync(0xffffffffu, sg, 2);
            sh += __shfl_xor_sync(0xffffffffu, sh, 1);
            sh += __shfl_xor_sync(0xffffffffu, sh, 2);
            if (tig == 0) {
                part[wid * 128 + mt * 16 + g]     = sg;
                part[wid * 128 + mt * 16 + 8 + g] = sh;
            }
        }
        __syncthreads();

        // per-row score + online softmax (threads 0..127)
        if (tid < 128) {
            int grow = tbase + tid;
            if (grow < NROWS) {
                float s = b2v;
                #pragma unroll
                for (int w = 0; w < 8; w++) s += part[w * 128 + tid];
                if (s > mx) {
                    float dd = fmaxf(mx - s, -87.f);
                    float e = expf(dd);
                    S1 = e * (S1 + dd * Z);
                    Z  = e * Z + 1.f;
                    mx = s;
                    arg = grow;
                } else {
                    float t = fmaxf(s - mx, -87.f);
                    float e = expf(t);
                    Z  += e;
                    S1 += t * e;
                }
            }
        }
        __syncthreads();
    }

    // block merge (reuse part)
    float* smx = part;
    float* sZ  = part + 256;
    float* sS1 = part + 512;
    int*   sarg = (int*)(part + 768);
    smx[tid] = mx; sZ[tid] = Z; sS1[tid] = S1; sarg[tid] = arg;
    __syncthreads();
    for (int s = 128; s; s >>= 1) {
        if (tid < s) {
            float qm = smx[tid + s], qZ = sZ[tid + s], qS = sS1[tid + s];
            int   qa = sarg[tid + s];
            if (qm > smx[tid] || (qm == smx[tid] && qa < sarg[tid])) {
                float d = fmaxf(smx[tid] - qm, -87.f);
                float e = expf(d);
                float Zo = sZ[tid], S1o = sS1[tid];
                sZ[tid]  = qZ + e * Zo;
                sS1[tid] = qS + e * (S1o + d * Zo);
                smx[tid] = qm; sarg[tid] = qa;
            } else {
                float d = fmaxf(qm - smx[tid], -87.f);
                float e = expf(d);
                sZ[tid]  += e * qZ;
                sS1[tid] += e * (qS + d * qZ);
            }
        }
        __syncthreads();
    }
    if (tid == 0) {
        g_wmax[blockIdx.x] = smx[0];
        g_warg[blockIdx.x] = sarg[0];
        g_wZ[blockIdx.x]   = sZ[0];
        g_wS1[blockIdx.x]  = sS1[0];
    }
}

// ---------------- K3: merge 296 block partials ----------------
__global__ void __launch_bounds__(512) finalize_kernel(float* __restrict__ out) {
    __shared__ float smx[512], sZ[512], sS1[512];
    __shared__ int   sarg[512];
    int tid = threadIdx.x;

    float mx = -3.402823466e38f, Z = 0.f, S1 = 0.f;
    int   arg = 0x7fffffff;
    if (tid < NWTOT) { mx = g_wmax[tid]; Z = g_wZ[tid]; S1 = g_wS1[tid]; arg = g_warg[tid]; }
    smx[tid] = mx; sarg[tid] = arg; sZ[tid] = Z; sS1[tid] = S1;
    __syncthreads();

    for (int s = 256; s; s >>= 1) {
        if (tid < s) {
            float qm = smx[tid + s], qZ = sZ[tid + s], qS = sS1[tid + s];
            int   qa = sarg[tid + s];
            if (qm > smx[tid] || (qm == smx[tid] && qa < sarg[tid])) {
                float d = fmaxf(smx[tid] - qm, -87.f);
                float e = expf(d);
                float Zo = sZ[tid], S1o = sS1[tid];
                sZ[tid]  = qZ + e * Zo;
                sS1[tid] = qS + e * (S1o + d * Zo);
                smx[tid] = qm; sarg[tid] = qa;
            } else {
                float d = fmaxf(qm - smx[tid], -87.f);
                float e = expf(d);
                sZ[tid]  += e * qZ;
                sS1[tid] += e * (qS + d * qZ);
            }
        }
        __syncthreads();
    }

    if (tid == 0) {
        float Zf = sZ[0], S1f = sS1[0];
        float logZ = logf(Zf);
        out[0] = (float)sarg[0];
        out[1] = 1.0f / Zf;          // p[idx]
        out[2] = -logZ;              // logp[idx]
        out[3] = logZ - S1f / Zf;    // entropy
    }
}

// ---------------- launch ----------------
extern "C" void kernel_launch(void* const* d_in, const int* in_sizes, int n_in,
                              void* d_out, int out_size) {
    const float* x_graph = (const float*)d_in[0];
    const float* x_m     = (const float*)d_in[1];
    const float* x_job   = (const float*)d_in[2];
    const int*   m_ids   = (const int*)  d_in[3];
    const int*   job_idx = (const int*)  d_in[4];
    const float* W0      = (const float*)d_in[5];
    const float* b0      = (const float*)d_in[6];
    const float* W1      = (const float*)d_in[7];
    const float* b1      = (const float*)d_in[8];
    const float* W2      = (const float*)d_in[9];
    const float* b2      = (const float*)d_in[10];
    float* out = (float*)d_out;

    cudaFuncSetAttribute(precompute_kernel,
                         cudaFuncAttributeMaxDynamicSharedMemorySize, P_SMEM);
    cudaFuncSetAttribute(score_kernel,
                         cudaFuncAttributeMaxDynamicSharedMemorySize, SMEM_SZ);

    precompute_kernel<<<NT_M + NT_J + 1, 256, P_SMEM>>>(x_graph, x_m, x_job, W0, b0);
    score_kernel<<<SBLOCKS, 256, SMEM_SZ>>>(m_ids, job_idx, W1, b1, W2, b2);
    finalize_kernel<<<1, 512>>>(out);
}